// round 1
// baseline (speedup 1.0000x reference)
#include <cuda_runtime.h>
#include <math.h>

#define BB 64
#define TT 2048
#define ENC_DIM 512
#define ATT_DIM 128
#define RNN_DIM 1024
#define N_FILT 32
#define KSIZE 31
#define PADC 15
#define WIN 32
#define WLMAX 65          // window length: 2*WIN + 1

__global__ __launch_bounds__(256, 1)
void attn_fused_kernel(
    const float* __restrict__ h,        // [B,1024]  attention_hidden_state
    const float* __restrict__ memory,   // [B,T,512]
    const float* __restrict__ pm,       // [B,T,128] processed_memory
    const float* __restrict__ awcat,    // [B,2,T]
    const unsigned char* __restrict__ maskp, // [B,T] bool
    const int* __restrict__ mlen,       // [B]
    const float* __restrict__ cpos,     // [B]
    const float* __restrict__ convw,    // [32,2,31]
    const float* __restrict__ densew,   // [128,32]
    const float* __restrict__ queryw,   // [128,1024]
    const float* __restrict__ vw,       // [1,128]
    const float* __restrict__ posoff,   // [1]
    float* __restrict__ out)            // ctx[64*512] | weights[64*2048] | new_pos[64]
{
    __shared__ float h_sh[RNN_DIM];                       // 4 KB
    __shared__ float q_sh[ATT_DIM];
    __shared__ float convw_sh[N_FILT * 2 * KSIZE];        // 7.75 KB
    __shared__ float dense_t_sh[N_FILT * ATT_DIM];        // 16 KB, transposed: [f][a]
    __shared__ float v_sh[ATT_DIM];
    __shared__ float aw_sh[2][WLMAX + KSIZE - 1];         // [2][95]
    __shared__ float conv_sh[WLMAX * N_FILT];             // 8.3 KB
    __shared__ float e_sh[WLMAX];
    __shared__ float w_sh[WLMAX];
    __shared__ int   s_start, s_wl, s_fallback;

    const int b    = blockIdx.x;
    const int tid  = threadIdx.x;
    const int lane = tid & 31;
    const int wid  = tid >> 5;

    // ---- stage constants / per-row vectors into shared ----
    for (int i = tid; i < RNN_DIM; i += 256)          h_sh[i] = h[b * RNN_DIM + i];
    for (int i = tid; i < N_FILT * 2 * KSIZE; i += 256) convw_sh[i] = convw[i];
    for (int i = tid; i < ATT_DIM * N_FILT; i += 256) {
        int a = i / N_FILT, f = i % N_FILT;           // densew is [a][f]
        dense_t_sh[f * ATT_DIM + a] = densew[i];      // store transposed [f][a]
    }
    if (tid < ATT_DIM) v_sh[tid] = vw[tid];

    // ---- window computation (replicates reference clamp/round semantics) ----
    if (tid == 0) {
        float cp      = cpos[b] + posoff[0];
        float max_end = (float)(mlen[b] - 1 - WIN);
        cp = fminf(fmaxf(cp, (float)WIN), max_end);
        float ms = rintf(fmaxf(cp - (float)WIN, 0.0f)); // round-half-even
        int start = (int)ms;
        if (start < 0) start = 0;
        if (start > TT - 1) start = TT - 1;
        int end = start + 2 * WIN;
        if (end > TT - 1) end = TT - 1;
        s_start = start;
        s_wl    = end - start + 1;
    }
    __syncthreads();
    const int start = s_start;
    const int wl    = s_wl;

    // ---- q = queryw @ h[b]  (warp-per-output, coalesced rows) ----
    for (int a = wid; a < ATT_DIM; a += 8) {
        const float* row = queryw + a * RNN_DIM;
        float acc = 0.f;
        for (int j = lane; j < RNN_DIM; j += 32) acc += row[j] * h_sh[j];
        #pragma unroll
        for (int o = 16; o; o >>= 1) acc += __shfl_down_sync(0xffffffffu, acc, o);
        if (lane == 0) q_sh[a] = acc;
    }

    // ---- stage attention_weights_cat window (with zero pad) ----
    const int awlen = wl + KSIZE - 1;
    for (int j = tid; j < 2 * awlen; j += 256) {
        int c = j / awlen, jj = j % awlen;
        int g = start - PADC + jj;
        aw_sh[c][jj] = (g >= 0 && g < TT) ? awcat[((size_t)b * 2 + c) * TT + g] : 0.f;
    }
    __syncthreads();

    // ---- location conv: conv[tl][f] ----
    for (int idx = tid; idx < wl * N_FILT; idx += 256) {
        int tl = idx >> 5, f = idx & 31;
        const float* w0 = convw_sh + f * 2 * KSIZE;
        float acc = 0.f;
        #pragma unroll
        for (int k = 0; k < KSIZE; k++) {
            acc += aw_sh[0][tl + k] * w0[k];
            acc += aw_sh[1][tl + k] * w0[KSIZE + k];
        }
        conv_sh[idx] = acc;
    }
    __syncthreads();

    // ---- energies: warp handles t = wid, wid+8, ... ----
    for (int tl = wid; tl < wl; tl += 8) {
        const int t = start + tl;
        const float* cv  = conv_sh + tl * N_FILT;
        const float* pmr = pm + ((size_t)b * TT + t) * ATT_DIM;
        float s0 = q_sh[lane]      + pmr[lane];
        float s1 = q_sh[lane + 32] + pmr[lane + 32];
        float s2 = q_sh[lane + 64] + pmr[lane + 64];
        float s3 = q_sh[lane + 96] + pmr[lane + 96];
        #pragma unroll
        for (int f = 0; f < N_FILT; f++) {
            const float c  = cv[f];                 // broadcast
            const float* dt = dense_t_sh + f * ATT_DIM;
            s0 += dt[lane]      * c;                // conflict-free
            s1 += dt[lane + 32] * c;
            s2 += dt[lane + 64] * c;
            s3 += dt[lane + 96] * c;
        }
        float acc = v_sh[lane]      * tanhf(s0)
                  + v_sh[lane + 32] * tanhf(s1)
                  + v_sh[lane + 64] * tanhf(s2)
                  + v_sh[lane + 96] * tanhf(s3);
        #pragma unroll
        for (int o = 16; o; o >>= 1) acc += __shfl_down_sync(0xffffffffu, acc, o);
        if (lane == 0)
            e_sh[tl] = maskp[(size_t)b * TT + t] ? -1e9f : acc;
    }
    __syncthreads();

    // ---- softmax over the window (serial in thread 0 — 65 elems, negligible) ----
    if (tid == 0) {
        float m = -INFINITY;
        for (int i = 0; i < wl; i++) m = fmaxf(m, e_sh[i]);
        if (m <= -1e9f) {
            s_fallback = 1;   // everything masked -> reference softmax is uniform 1/T
        } else {
            s_fallback = 0;
            float sum = 0.f;
            for (int i = 0; i < wl; i++) { float ev = __expf ? expf(e_sh[i] - m) : 0.f; w_sh[i] = ev; sum += ev; }
            float inv = 1.f / sum;
            for (int i = 0; i < wl; i++) w_sh[i] *= inv;
        }
    }
    __syncthreads();

    float* out_ctx = out + (size_t)b * ENC_DIM;
    float* out_w   = out + (size_t)BB * ENC_DIM + (size_t)b * TT;
    float* out_np  = out + (size_t)BB * ENC_DIM + (size_t)BB * TT;

    if (!s_fallback) {
        // attention_weights: exact zeros outside window (matches expf underflow)
        for (int t = tid; t < TT; t += 256) {
            int tl = t - start;
            out_w[t] = (tl >= 0 && tl < wl) ? w_sh[tl] : 0.0f;
        }
        // new_pos
        if (tid == 0) {
            float np = 0.f;
            for (int i = 0; i < wl; i++) np += w_sh[i] * (float)(start + i);
            out_np[b] = np;
        }
        // context: 128 threads x float4 over ENC_DIM
        if (tid < 128) {
            const float4* mem4 = (const float4*)(memory + (size_t)b * TT * ENC_DIM);
            float4 acc = make_float4(0.f, 0.f, 0.f, 0.f);
            for (int i = 0; i < wl; i++) {
                const float wv = w_sh[i];
                const float4 m4 = mem4[(size_t)(start + i) * (ENC_DIM / 4) + tid];
                acc.x += wv * m4.x; acc.y += wv * m4.y;
                acc.z += wv * m4.z; acc.w += wv * m4.w;
            }
            ((float4*)out_ctx)[tid] = acc;
        }
    } else {
        // uniform softmax fallback (fully-masked row) — slow path, rarely taken
        const float u = 1.0f / (float)TT;
        for (int t = tid; t < TT; t += 256) out_w[t] = u;
        if (tid == 0) out_np[b] = (float)(TT - 1) * 0.5f;
        if (tid < 128) {
            const float4* mem4 = (const float4*)(memory + (size_t)b * TT * ENC_DIM);
            float4 acc = make_float4(0.f, 0.f, 0.f, 0.f);
            for (int t = 0; t < TT; t++) {
                const float4 m4 = mem4[(size_t)t * (ENC_DIM / 4) + tid];
                acc.x += m4.x; acc.y += m4.y; acc.z += m4.z; acc.w += m4.w;
            }
            acc.x *= u; acc.y *= u; acc.z *= u; acc.w *= u;
            ((float4*)out_ctx)[tid] = acc;
        }
    }
}

extern "C" void kernel_launch(void* const* d_in, const int* in_sizes, int n_in,
                              void* d_out, int out_size) {
    const float*         h      = (const float*)d_in[0];   // [64,1024]
    const float*         memory = (const float*)d_in[1];   // [64,2048,512]
    const float*         pm     = (const float*)d_in[2];   // [64,2048,128]
    const float*         awcat  = (const float*)d_in[3];   // [64,2,2048]
    const unsigned char* maskp  = (const unsigned char*)d_in[4]; // [64,2048] bool
    const int*           mlen   = (const int*)d_in[5];     // [64]
    const float*         cpos   = (const float*)d_in[6];   // [64]
    const float*         convw  = (const float*)d_in[7];   // [32,2,31]
    const float*         densew = (const float*)d_in[8];   // [128,32]
    const float*         queryw = (const float*)d_in[9];   // [128,1024]
    const float*         vw     = (const float*)d_in[10];  // [1,128]
    const float*         posoff = (const float*)d_in[11];  // [1]
    float* out = (float*)d_out;

    attn_fused_kernel<<<BB, 256>>>(h, memory, pm, awcat, maskp, mlen, cpos,
                                   convw, densew, queryw, vw, posoff, out);
}

// round 2
// speedup vs baseline: 1.2443x; 1.2443x over previous
#include <cuda_runtime.h>
#include <math.h>

#define BB 64
#define TT 2048
#define ENC_DIM 512
#define ATT_DIM 128
#define RNN_DIM 1024
#define N_FILT 32
#define KSIZE 31
#define PADC 15
#define WIN 32
#define WLMAX 65
#define WLP 66          // padded conv row stride

// ---- dynamic smem layout (in floats) ----
#define F_MEM  0
#define F_PM   (F_MEM + WLMAX * ENC_DIM)          // 33280
#define F_DT   (F_PM + WLMAX * ATT_DIM)           // 41600
#define F_CW   (F_DT + N_FILT * ATT_DIM)          // 45696
#define F_H    (F_CW + N_FILT * 2 * KSIZE)        // 47680
#define F_CONV (F_H + RNN_DIM)                    // 48704
#define F_AW   (F_CONV + N_FILT * WLP)            // 50816
#define F_Q    (F_AW + 2 * 96)                    // 51008
#define F_V    (F_Q + ATT_DIM)                    // 51136
#define F_E    (F_V + ATT_DIM)                    // 51264
#define F_MK   (F_E + 72)                         // 51336
#define F_W    (F_MK + 72)                        // 51408
#define F_END  (F_W + 72)                         // 51480
#define SMEM_BYTES (F_END * 4)                    // 205,920 B

__device__ __forceinline__ float ftanh(float x) {
    float a = fabsf(x);
    float t = __expf(-2.0f * a);
    float r = __fdividef(1.0f - t, 1.0f + t);
    return copysignf(r, x);
}

__device__ __forceinline__ void cp16(unsigned dst, const void* src) {
    asm volatile("cp.async.cg.shared.global [%0], [%1], 16;" :: "r"(dst), "l"(src));
}

__global__ __launch_bounds__(256, 1)
void attn_fused_kernel(
    const float* __restrict__ h,
    const float* __restrict__ memory,
    const float* __restrict__ pm,
    const float* __restrict__ awcat,
    const unsigned char* __restrict__ maskp,
    const int* __restrict__ mlen,
    const float* __restrict__ cpos,
    const float* __restrict__ convw,
    const float* __restrict__ densew,
    const float* __restrict__ queryw,
    const float* __restrict__ vw,
    const float* __restrict__ posoff,
    float* __restrict__ out)
{
    extern __shared__ float sm[];
    __shared__ int s_start, s_wl, s_fb;

    const int b    = blockIdx.x;
    const int tid  = threadIdx.x;
    const int lane = tid & 31;
    const int wid  = tid >> 5;

    float* mem_sh  = sm + F_MEM;
    float* pm_sh   = sm + F_PM;
    float* dense_t = sm + F_DT;
    float* cw_sh   = sm + F_CW;
    float* h_sh    = sm + F_H;
    float* conv_sh = sm + F_CONV;
    float* aw0_sh  = sm + F_AW;
    float* aw1_sh  = sm + F_AW + 96;
    float* q_sh    = sm + F_Q;
    float* v_sh    = sm + F_V;
    float* e_sh    = sm + F_E;
    float* mk_sh   = sm + F_MK;
    float* w_sh    = sm + F_W;

    // ---- phase 0: window + static staging (no start dependency) ----
    if (tid == 0) {
        float cp      = cpos[b] + posoff[0];
        float max_end = (float)(mlen[b] - 1 - WIN);
        cp = fminf(fmaxf(cp, (float)WIN), max_end);
        float ms = rintf(fmaxf(cp - (float)WIN, 0.0f));
        int start = (int)ms;
        if (start < 0) start = 0;
        if (start > TT - 1) start = TT - 1;
        int end = start + 2 * WIN;
        if (end > TT - 1) end = TT - 1;
        s_start = start;
        s_wl    = end - start + 1;
    }
    // h (float4), conv weights, dense (transposed), v
    {
        const float4* hg = (const float4*)(h + (size_t)b * RNN_DIM);
        float4* h4 = (float4*)h_sh;
        if (tid < 256) h4[tid] = hg[tid];
        for (int i = tid; i < N_FILT * 2 * KSIZE; i += 256) cw_sh[i] = convw[i];
        for (int i = tid; i < ATT_DIM * N_FILT; i += 256) {
            int a = i >> 5, f = i & 31;
            dense_t[f * ATT_DIM + a] = densew[i];
        }
        if (tid < ATT_DIM) v_sh[tid] = vw[tid];
    }
    __syncthreads();
    const int start = s_start;
    const int wl    = s_wl;

    // ---- phase 1: async prefetch of pm + memory windows; stage aw/mask ----
    {
        const unsigned pm_base  = (unsigned)__cvta_generic_to_shared(pm_sh);
        const unsigned mem_base = (unsigned)__cvta_generic_to_shared(mem_sh);
        const float4* pmsrc  = (const float4*)(pm + ((size_t)b * TT + start) * ATT_DIM);
        const float4* memsrc = (const float4*)(memory + ((size_t)b * TT + start) * ENC_DIM);
        const int n_pm4 = wl * (ATT_DIM / 4);
        for (int i = tid; i < n_pm4; i += 256) cp16(pm_base + i * 16, pmsrc + i);
        asm volatile("cp.async.commit_group;");
        const int n_m4 = wl * (ENC_DIM / 4);
        for (int i = tid; i < n_m4; i += 256) cp16(mem_base + i * 16, memsrc + i);
        asm volatile("cp.async.commit_group;");

        const int awlen = wl + KSIZE - 1;
        for (int j = tid; j < 2 * awlen; j += 256) {
            int c = (j >= awlen), jj = c ? j - awlen : j;
            int g = start - PADC + jj;
            float v = (g >= 0 && g < TT) ? awcat[((size_t)b * 2 + c) * TT + g] : 0.f;
            (c ? aw1_sh : aw0_sh)[jj] = v;
        }
        if (tid < wl) mk_sh[tid] = maskp[(size_t)b * TT + start + tid] ? 1.f : 0.f;
    }

    // ---- phase 2: query GEMV (q = queryw @ h), float4 + 2-row ILP ----
    {
        const float4* h4 = (const float4*)h_sh;
        const int a0base = wid * 16;
        for (int a0 = a0base; a0 < a0base + 16; a0 += 2) {
            const float4* r0 = (const float4*)(queryw + (size_t)a0 * RNN_DIM);
            const float4* r1 = (const float4*)(queryw + (size_t)(a0 + 1) * RNN_DIM);
            float acc0 = 0.f, acc1 = 0.f;
            #pragma unroll
            for (int k = 0; k < 8; k++) {
                float4 hv = h4[lane + k * 32];
                float4 w0 = r0[lane + k * 32];
                float4 w1 = r1[lane + k * 32];
                acc0 += hv.x * w0.x + hv.y * w0.y + hv.z * w0.z + hv.w * w0.w;
                acc1 += hv.x * w1.x + hv.y * w1.y + hv.z * w1.z + hv.w * w1.w;
            }
            #pragma unroll
            for (int o = 16; o; o >>= 1) {
                acc0 += __shfl_down_sync(0xffffffffu, acc0, o);
                acc1 += __shfl_down_sync(0xffffffffu, acc1, o);
            }
            if (lane == 0) { q_sh[a0] = acc0; q_sh[a0 + 1] = acc1; }
        }
    }
    __syncthreads();   // aw_sh + q_sh ready

    // ---- phase 3: location conv: conv_sh[f*WLP + tl] ----
    for (int f = wid; f < N_FILT; f += 8) {
        const float* w0 = cw_sh + f * 2 * KSIZE;
        const float* w1 = w0 + KSIZE;
        for (int tl = lane; tl < wl; tl += 32) {
            float acc = 0.f;
            #pragma unroll
            for (int k = 0; k < KSIZE; k++)
                acc += aw0_sh[tl + k] * w0[k] + aw1_sh[tl + k] * w1[k];
            conv_sh[f * WLP + tl] = acc;
        }
    }
    asm volatile("cp.async.wait_group 1;");   // pm window ready (this thread)
    __syncthreads();                          // everyone's pm cp.asyncs + conv done

    // ---- phase 4: energies (2-timestep register blocking) ----
    {
        const float qv0 = q_sh[lane],      qv1 = q_sh[lane + 32];
        const float qv2 = q_sh[lane + 64], qv3 = q_sh[lane + 96];
        const float vv0 = v_sh[lane],      vv1 = v_sh[lane + 32];
        const float vv2 = v_sh[lane + 64], vv3 = v_sh[lane + 96];
        for (int base = wid * 2; base < wl; base += 16) {
            const int t0 = base;
            const int t1 = (base + 1 < wl) ? base + 1 : base;
            const bool has1 = (base + 1 < wl);
            const float* p0 = pm_sh + t0 * ATT_DIM;
            const float* p1 = pm_sh + t1 * ATT_DIM;
            float s00 = qv0 + p0[lane],      s01 = qv1 + p0[lane + 32];
            float s02 = qv2 + p0[lane + 64], s03 = qv3 + p0[lane + 96];
            float s10 = qv0 + p1[lane],      s11 = qv1 + p1[lane + 32];
            float s12 = qv2 + p1[lane + 64], s13 = qv3 + p1[lane + 96];
            #pragma unroll
            for (int f = 0; f < N_FILT; f++) {
                const float c0 = conv_sh[f * WLP + t0];
                const float c1 = conv_sh[f * WLP + t1];
                const float* dt = dense_t + f * ATT_DIM;
                const float d0 = dt[lane],      d1 = dt[lane + 32];
                const float d2 = dt[lane + 64], d3 = dt[lane + 96];
                s00 += d0 * c0; s01 += d1 * c0; s02 += d2 * c0; s03 += d3 * c0;
                s10 += d0 * c1; s11 += d1 * c1; s12 += d2 * c1; s13 += d3 * c1;
            }
            float a0 = vv0 * ftanh(s00) + vv1 * ftanh(s01) + vv2 * ftanh(s02) + vv3 * ftanh(s03);
            float a1 = vv0 * ftanh(s10) + vv1 * ftanh(s11) + vv2 * ftanh(s12) + vv3 * ftanh(s13);
            #pragma unroll
            for (int o = 16; o; o >>= 1) {
                a0 += __shfl_down_sync(0xffffffffu, a0, o);
                a1 += __shfl_down_sync(0xffffffffu, a1, o);
            }
            if (lane == 0) {
                e_sh[t0] = (mk_sh[t0] != 0.f) ? -1e9f : a0;
                if (has1) e_sh[t1] = (mk_sh[t1] != 0.f) ? -1e9f : a1;
            }
        }
    }
    __syncthreads();

    // ---- phase 5: parallel softmax + new_pos (warp 0) ----
    if (wid == 0) {
        float e0 = (lane < wl)      ? e_sh[lane]      : -3.4e38f;
        float e1 = (lane + 32 < wl) ? e_sh[lane + 32] : -3.4e38f;
        float e2 = (lane + 64 < wl) ? e_sh[lane + 64] : -3.4e38f;
        float m = fmaxf(e0, fmaxf(e1, e2));
        #pragma unroll
        for (int o = 16; o; o >>= 1) m = fmaxf(m, __shfl_xor_sync(0xffffffffu, m, o));
        if (m <= -1e9f) {
            if (lane == 0) s_fb = 1;
        } else {
            if (lane == 0) s_fb = 0;
            float x0 = (lane < wl)      ? __expf(e0 - m) : 0.f;
            float x1 = (lane + 32 < wl) ? __expf(e1 - m) : 0.f;
            float x2 = (lane + 64 < wl) ? __expf(e2 - m) : 0.f;
            float ssum = x0 + x1 + x2;
            float np = x0 * (float)(start + lane)
                     + x1 * (float)(start + lane + 32)
                     + x2 * (float)(start + lane + 64);
            #pragma unroll
            for (int o = 16; o; o >>= 1) {
                ssum += __shfl_xor_sync(0xffffffffu, ssum, o);
                np   += __shfl_xor_sync(0xffffffffu, np, o);
            }
            float inv = __fdividef(1.0f, ssum);
            if (lane < wl)      w_sh[lane]      = x0 * inv;
            if (lane + 32 < wl) w_sh[lane + 32] = x1 * inv;
            if (lane + 64 < wl) w_sh[lane + 64] = x2 * inv;
            if (lane == 0)
                out[(size_t)BB * ENC_DIM + (size_t)BB * TT + b] = np * inv;
        }
    }
    asm volatile("cp.async.wait_group 0;");   // memory window ready
    __syncthreads();

    float* out_ctx = out + (size_t)b * ENC_DIM;
    float* out_w   = out + (size_t)BB * ENC_DIM + (size_t)b * TT;

    if (!s_fb) {
        // weights (exact zeros outside window = expf underflow in reference)
        #pragma unroll
        for (int t = tid; t < TT; t += 256) {
            int tl = t - start;
            out_w[t] = (tl >= 0 && tl < wl) ? w_sh[tl] : 0.0f;
        }
        // context from smem window: 256 threads = 128 cols x 2 window halves
        const int c  = tid & 127;
        const int hf = tid >> 7;
        const int i0 = hf ? 33 : 0;
        const int i1 = hf ? wl : (wl < 33 ? wl : 33);
        const float4* m4 = (const float4*)mem_sh;
        float4 acc = make_float4(0.f, 0.f, 0.f, 0.f);
        #pragma unroll 4
        for (int i = i0; i < i1; i++) {
            const float wv = w_sh[i];
            const float4 v = m4[i * (ENC_DIM / 4) + c];
            acc.x += wv * v.x; acc.y += wv * v.y;
            acc.z += wv * v.z; acc.w += wv * v.w;
        }
        float4* part = (float4*)conv_sh;   // conv_sh dead now
        if (hf) part[c] = acc;
        __syncthreads();
        if (!hf) {
            const float4 p = part[c];
            acc.x += p.x; acc.y += p.y; acc.z += p.z; acc.w += p.w;
            ((float4*)out_ctx)[c] = acc;
        }
    } else {
        // fully-masked row: reference softmax is uniform over all T
        const float u = 1.0f / (float)TT;
        for (int t = tid; t < TT; t += 256) out_w[t] = u;
        if (tid == 0)
            out[(size_t)BB * ENC_DIM + (size_t)BB * TT + b] = (float)(TT - 1) * 0.5f;
        if (tid < 128) {
            const float4* mg = (const float4*)(memory + (size_t)b * TT * ENC_DIM);
            float4 acc = make_float4(0.f, 0.f, 0.f, 0.f);
            for (int t = 0; t < TT; t++) {
                const float4 v = mg[(size_t)t * (ENC_DIM / 4) + tid];
                acc.x += v.x; acc.y += v.y; acc.z += v.z; acc.w += v.w;
            }
            acc.x *= u; acc.y *= u; acc.z *= u; acc.w *= u;
            ((float4*)out_ctx)[tid] = acc;
        }
        __syncthreads();  // match barrier in fast path
    }
}

extern "C" void kernel_launch(void* const* d_in, const int* in_sizes, int n_in,
                              void* d_out, int out_size) {
    const float*         h      = (const float*)d_in[0];
    const float*         memory = (const float*)d_in[1];
    const float*         pm     = (const float*)d_in[2];
    const float*         awcat  = (const float*)d_in[3];
    const unsigned char* maskp  = (const unsigned char*)d_in[4];
    const int*           mlen   = (const int*)d_in[5];
    const float*         cpos   = (const float*)d_in[6];
    const float*         convw  = (const float*)d_in[7];
    const float*         densew = (const float*)d_in[8];
    const float*         queryw = (const float*)d_in[9];
    const float*         vw     = (const float*)d_in[10];
    const float*         posoff = (const float*)d_in[11];
    float* out = (float*)d_out;

    cudaFuncSetAttribute(attn_fused_kernel,
                         cudaFuncAttributeMaxDynamicSharedMemorySize, SMEM_BYTES);
    attn_fused_kernel<<<BB, 256, SMEM_BYTES>>>(h, memory, pm, awcat, maskp, mlen,
                                               cpos, convw, densew, queryw, vw,
                                               posoff, out);
}

// round 8
// speedup vs baseline: 1.4272x; 1.1470x over previous
#include <cuda_runtime.h>
#include <math.h>

#define BB 64
#define TT 2048
#define ENC_DIM 512
#define ATT_DIM 128
#define RNN_DIM 1024
#define N_FILT 32
#define KSIZE 31
#define PADC 15
#define WIN 32
#define WLMAX 65
#define WLP 68            // conv row stride (multiple of 4 for LDS.128)
#define DTP 129           // dense_t row stride (conflict-free both ways)
#define PM_ROWS 68        // padded so clamped t<=67 reads stay in-region

// ---- dynamic smem layout (floats) ----
#define F_MEM  0
#define F_PM   (F_MEM + WLMAX * ENC_DIM)            // 33280
#define F_DT   (F_PM + PM_ROWS * ATT_DIM)           // +8704
#define F_CWT  (F_DT + N_FILT * DTP)                // +4128  cwT[k][c][f]
#define F_H    (F_CWT + KSIZE * 2 * N_FILT)         // +1984
#define F_CONV (F_H + RNN_DIM)                      // +1024
#define F_AW   (F_CONV + N_FILT * WLP)              // +2176
#define F_Q    (F_AW + 2 * 96)                      // +192
#define F_V    (F_Q + ATT_DIM)
#define F_E    (F_V + ATT_DIM)
#define F_MK   (F_E + 72)
#define F_W    (F_MK + 72)
#define F_END  (F_W + 72)
#define SMEM_BYTES (F_END * 4)

__device__ __forceinline__ float ftanh(float x) {
    float a = fabsf(x);
    float t = __expf(-2.0f * a);
    float r = __fdividef(1.0f - t, 1.0f + t);
    return copysignf(r, x);
}

__device__ __forceinline__ void cp16(unsigned dst, const void* src) {
    asm volatile("cp.async.cg.shared.global [%0], [%1], 16;" :: "r"(dst), "l"(src));
}

__global__ __launch_bounds__(256, 1)
void attn_fused_kernel(
    const float* __restrict__ h,
    const float* __restrict__ memory,
    const float* __restrict__ pm,
    const float* __restrict__ awcat,
    const unsigned char* __restrict__ maskp,
    const int* __restrict__ mlen,
    const float* __restrict__ cpos,
    const float* __restrict__ convw,
    const float* __restrict__ densew,
    const float* __restrict__ queryw,
    const float* __restrict__ vw,
    const float* __restrict__ posoff,
    float* __restrict__ out)
{
    extern __shared__ float sm[];
    __shared__ int s_start, s_wl, s_fb;

    const int b    = blockIdx.x;
    const int tid  = threadIdx.x;
    const int lane = tid & 31;
    const int wid  = tid >> 5;

    float* mem_sh  = sm + F_MEM;
    float* pm_sh   = sm + F_PM;
    float* dense_t = sm + F_DT;
    float* cwt_sh  = sm + F_CWT;
    float* h_sh    = sm + F_H;
    float* conv_sh = sm + F_CONV;
    float* aw0_sh  = sm + F_AW;
    float* aw1_sh  = sm + F_AW + 96;
    float* q_sh    = sm + F_Q;
    float* v_sh    = sm + F_V;
    float* e_sh    = sm + F_E;
    float* mk_sh   = sm + F_MK;
    float* w_sh    = sm + F_W;

    // ---- phase 0: window + static staging ----
    if (tid == 0) {
        float cp      = cpos[b] + posoff[0];
        float max_end = (float)(mlen[b] - 1 - WIN);
        cp = fminf(fmaxf(cp, (float)WIN), max_end);
        float ms = rintf(fmaxf(cp - (float)WIN, 0.0f));
        int start = (int)ms;
        if (start < 0) start = 0;
        if (start > TT - 1) start = TT - 1;
        int end = start + 2 * WIN;
        if (end > TT - 1) end = TT - 1;
        s_start = start;
        s_wl    = end - start + 1;
    }
    {
        const float4* hg = (const float4*)(h + (size_t)b * RNN_DIM);
        ((float4*)h_sh)[tid] = hg[tid];
        // convw [f][c][k] -> cwT[k][c][f]
        for (int i = tid; i < N_FILT * 2 * KSIZE; i += 256) {
            int f = i / (2 * KSIZE), r = i % (2 * KSIZE);
            int c = r / KSIZE, k = r % KSIZE;
            cwt_sh[(k * 2 + c) * N_FILT + f] = convw[i];
        }
        // densew [a][f] -> dense_t[f][a] (stride DTP)
        for (int i = tid; i < ATT_DIM * N_FILT; i += 256) {
            int a = i >> 5, f = i & 31;
            dense_t[f * DTP + a] = densew[i];
        }
        if (tid < ATT_DIM) v_sh[tid] = vw[tid];
    }
    __syncthreads();
    const int start = s_start;
    const int wl    = s_wl;

    // ---- phase 1: async prefetch pm + memory windows; stage aw + mask ----
    {
        const unsigned pm_base  = (unsigned)__cvta_generic_to_shared(pm_sh);
        const unsigned mem_base = (unsigned)__cvta_generic_to_shared(mem_sh);
        const float4* pmsrc  = (const float4*)(pm + ((size_t)b * TT + start) * ATT_DIM);
        const float4* memsrc = (const float4*)(memory + ((size_t)b * TT + start) * ENC_DIM);
        const int n_pm4 = wl * (ATT_DIM / 4);
        for (int i = tid; i < n_pm4; i += 256) cp16(pm_base + i * 16, pmsrc + i);
        asm volatile("cp.async.commit_group;");
        const int n_m4 = wl * (ENC_DIM / 4);
        for (int i = tid; i < n_m4; i += 256) cp16(mem_base + i * 16, memsrc + i);
        asm volatile("cp.async.commit_group;");

        const int awlen = wl + KSIZE - 1;
        for (int j = tid; j < 2 * awlen; j += 256) {
            int c = (j >= awlen), jj = c ? j - awlen : j;
            int g = start - PADC + jj;
            float v = (g >= 0 && g < TT) ? awcat[((size_t)b * 2 + c) * TT + g] : 0.f;
            (c ? aw1_sh : aw0_sh)[jj] = v;
        }
        if (tid < wl) mk_sh[tid] = maskp[(size_t)b * TT + start + tid] ? 1.f : 0.f;
    }
    __syncthreads();   // aw/mask staged; h ready

    // ---- phase 2 (specialized): warps 0-3 GEMV | warps 4-7 conv ----
    if (wid < 4) {
        // q = queryw @ h : 32 rows per warp, 4-row ILP
        const float4* h4 = (const float4*)h_sh;
        #pragma unroll 1
        for (int g = 0; g < 8; g++) {
            const int a0 = wid * 32 + g * 4;
            const float4* r0 = (const float4*)(queryw + (size_t)a0 * RNN_DIM);
            const float4* r1 = (const float4*)(queryw + (size_t)(a0 + 1) * RNN_DIM);
            const float4* r2 = (const float4*)(queryw + (size_t)(a0 + 2) * RNN_DIM);
            const float4* r3 = (const float4*)(queryw + (size_t)(a0 + 3) * RNN_DIM);
            float acc0 = 0.f, acc1 = 0.f, acc2 = 0.f, acc3 = 0.f;
            #pragma unroll
            for (int k = 0; k < 8; k++) {
                const int idx = lane + k * 32;
                float4 hv = h4[idx];
                float4 w0 = r0[idx], w1 = r1[idx], w2 = r2[idx], w3 = r3[idx];
                acc0 += hv.x * w0.x + hv.y * w0.y + hv.z * w0.z + hv.w * w0.w;
                acc1 += hv.x * w1.x + hv.y * w1.y + hv.z * w1.z + hv.w * w1.w;
                acc2 += hv.x * w2.x + hv.y * w2.y + hv.z * w2.z + hv.w * w2.w;
                acc3 += hv.x * w3.x + hv.y * w3.y + hv.z * w3.z + hv.w * w3.w;
            }
            #pragma unroll
            for (int o = 16; o; o >>= 1) {
                acc0 += __shfl_down_sync(0xffffffffu, acc0, o);
                acc1 += __shfl_down_sync(0xffffffffu, acc1, o);
                acc2 += __shfl_down_sync(0xffffffffu, acc2, o);
                acc3 += __shfl_down_sync(0xffffffffu, acc3, o);
            }
            if (lane == 0) {
                q_sh[a0] = acc0; q_sh[a0 + 1] = acc1;
                q_sh[a0 + 2] = acc2; q_sh[a0 + 3] = acc3;
            }
        }
    } else {
        // conv: 8 filters per warp, lane = tl, k-inner with vectorized weight bcast
        const int f0 = (wid - 4) * 8;
        for (int tl = lane; tl < WLMAX; tl += 32) {   // full 65 (garbage rows masked later)
            float acc[8] = {0,0,0,0,0,0,0,0};
            #pragma unroll
            for (int k = 0; k < KSIZE; k++) {
                const float a0v = aw0_sh[tl + k];
                const float a1v = aw1_sh[tl + k];
                const float4 wq00 = *(const float4*)(cwt_sh + (k * 2 + 0) * N_FILT + f0);
                const float4 wq01 = *(const float4*)(cwt_sh + (k * 2 + 0) * N_FILT + f0 + 4);
                const float4 wq10 = *(const float4*)(cwt_sh + (k * 2 + 1) * N_FILT + f0);
                const float4 wq11 = *(const float4*)(cwt_sh + (k * 2 + 1) * N_FILT + f0 + 4);
                acc[0] += a0v * wq00.x + a1v * wq10.x;
                acc[1] += a0v * wq00.y + a1v * wq10.y;
                acc[2] += a0v * wq00.z + a1v * wq10.z;
                acc[3] += a0v * wq00.w + a1v * wq10.w;
                acc[4] += a0v * wq01.x + a1v * wq11.x;
                acc[5] += a0v * wq01.y + a1v * wq11.y;
                acc[6] += a0v * wq01.z + a1v * wq11.z;
                acc[7] += a0v * wq01.w + a1v * wq11.w;
            }
            #pragma unroll
            for (int j = 0; j < 8; j++) conv_sh[(f0 + j) * WLP + tl] = acc[j];
        }
    }
    asm volatile("cp.async.wait_group 1;");   // pm window complete
    __syncthreads();                          // q_sh + conv_sh ready

    // ---- phase 3: energies, 4-timestep x 4-attdim register blocking ----
    {
        const float qv0 = q_sh[lane],      qv1 = q_sh[lane + 32];
        const float qv2 = q_sh[lane + 64], qv3 = q_sh[lane + 96];
        const float vv0 = v_sh[lane],      vv1 = v_sh[lane + 32];
        const float vv2 = v_sh[lane + 64], vv3 = v_sh[lane + 96];
        for (int t0 = wid * 4; t0 < wl; t0 += 32) {
            float s[4][4];
            #pragma unroll
            for (int i = 0; i < 4; i++) {
                const float* p = pm_sh + (t0 + i) * ATT_DIM;   // padded region: safe
                s[i][0] = qv0 + p[lane];
                s[i][1] = qv1 + p[lane + 32];
                s[i][2] = qv2 + p[lane + 64];
                s[i][3] = qv3 + p[lane + 96];
            }
            #pragma unroll
            for (int f = 0; f < N_FILT; f++) {
                const float4 c4 = *(const float4*)(conv_sh + f * WLP + t0); // bcast
                const float* dt = dense_t + f * DTP;
                const float d0 = dt[lane],      d1 = dt[lane + 32];
                const float d2 = dt[lane + 64], d3 = dt[lane + 96];
                s[0][0] += d0 * c4.x; s[0][1] += d1 * c4.x; s[0][2] += d2 * c4.x; s[0][3] += d3 * c4.x;
                s[1][0] += d0 * c4.y; s[1][1] += d1 * c4.y; s[1][2] += d2 * c4.y; s[1][3] += d3 * c4.y;
                s[2][0] += d0 * c4.z; s[2][1] += d1 * c4.z; s[2][2] += d2 * c4.z; s[2][3] += d3 * c4.z;
                s[3][0] += d0 * c4.w; s[3][1] += d1 * c4.w; s[3][2] += d2 * c4.w; s[3][3] += d3 * c4.w;
            }
            float a[4];
            #pragma unroll
            for (int i = 0; i < 4; i++)
                a[i] = vv0 * ftanh(s[i][0]) + vv1 * ftanh(s[i][1])
                     + vv2 * ftanh(s[i][2]) + vv3 * ftanh(s[i][3]);
            // butterfly: ALL lanes end with the full sums (lanes 0-3 each write one)
            #pragma unroll
            for (int o = 16; o; o >>= 1) {
                a[0] += __shfl_xor_sync(0xffffffffu, a[0], o);
                a[1] += __shfl_xor_sync(0xffffffffu, a[1], o);
                a[2] += __shfl_xor_sync(0xffffffffu, a[2], o);
                a[3] += __shfl_xor_sync(0xffffffffu, a[3], o);
            }
            if (lane < 4 && t0 + lane < wl) {
                float av = (lane == 0) ? a[0] : (lane == 1) ? a[1] : (lane == 2) ? a[2] : a[3];
                e_sh[t0 + lane] = (mk_sh[t0 + lane] != 0.f) ? -1e9f : av;
            }
        }
    }
    __syncthreads();

    float* out_ctx = out + (size_t)b * ENC_DIM;
    float* out_w   = out + (size_t)BB * ENC_DIM + (size_t)b * TT;

    // ---- phase 4: softmax+new_pos (warp 0) || zero-fill out_w (warps 1-7) ----
    if (wid == 0) {
        float e0 = (lane < wl)      ? e_sh[lane]      : -3.4e38f;
        float e1 = (lane + 32 < wl) ? e_sh[lane + 32] : -3.4e38f;
        float e2 = (lane + 64 < wl) ? e_sh[lane + 64] : -3.4e38f;
        float m = fmaxf(e0, fmaxf(e1, e2));
        #pragma unroll
        for (int o = 16; o; o >>= 1) m = fmaxf(m, __shfl_xor_sync(0xffffffffu, m, o));
        if (m <= -1e9f) {
            if (lane == 0) s_fb = 1;
        } else {
            if (lane == 0) s_fb = 0;
            float x0 = (lane < wl)      ? __expf(e0 - m) : 0.f;
            float x1 = (lane + 32 < wl) ? __expf(e1 - m) : 0.f;
            float x2 = (lane + 64 < wl) ? __expf(e2 - m) : 0.f;
            float ssum = x0 + x1 + x2;
            float np = x0 * (float)(start + lane)
                     + x1 * (float)(start + lane + 32)
                     + x2 * (float)(start + lane + 64);
            #pragma unroll
            for (int o = 16; o; o >>= 1) {
                ssum += __shfl_xor_sync(0xffffffffu, ssum, o);
                np   += __shfl_xor_sync(0xffffffffu, np, o);
            }
            float inv = __fdividef(1.0f, ssum);
            if (lane < wl)      w_sh[lane]      = x0 * inv;
            if (lane + 32 < wl) w_sh[lane + 32] = x1 * inv;
            if (lane + 64 < wl) w_sh[lane + 64] = x2 * inv;
            if (lane == 0)
                out[(size_t)BB * ENC_DIM + (size_t)BB * TT + b] = np * inv;
        }
    } else {
        // zero whole weight row with float4 (window overwritten after barrier)
        float4* w4 = (float4*)out_w;
        const int t4 = tid - 32;                  // 0..223
        const float4 z = make_float4(0.f, 0.f, 0.f, 0.f);
        for (int i = t4; i < TT / 4; i += 224) w4[i] = z;
    }
    asm volatile("cp.async.wait_group 0;");   // memory window complete
    __syncthreads();

    if (!s_fb) {
        if (tid < wl) out_w[start + tid] = w_sh[tid];
        // context: 256 threads = 128 cols x 2 window halves
        const int c  = tid & 127;
        const int hf = tid >> 7;
        const int i0 = hf ? 33 : 0;
        const int i1 = hf ? wl : (wl < 33 ? wl : 33);
        const float4* m4 = (const float4*)mem_sh;
        float4 acc = make_float4(0.f, 0.f, 0.f, 0.f);
        #pragma unroll 4
        for (int i = i0; i < i1; i++) {
            const float wv = w_sh[i];
            const float4 v = m4[i * (ENC_DIM / 4) + c];
            acc.x += wv * v.x; acc.y += wv * v.y;
            acc.z += wv * v.z; acc.w += wv * v.w;
        }
        float4* part = (float4*)conv_sh;   // conv_sh dead
        if (hf) part[c] = acc;
        __syncthreads();
        if (!hf) {
            const float4 p = part[c];
            acc.x += p.x; acc.y += p.y; acc.z += p.z; acc.w += p.w;
            ((float4*)out_ctx)[c] = acc;
        }
    } else {
        const float u = 1.0f / (float)TT;
        for (int t = tid; t < TT; t += 256) out_w[t] = u;
        if (tid == 0)
            out[(size_t)BB * ENC_DIM + (size_t)BB * TT + b] = (float)(TT - 1) * 0.5f;
        if (tid < 128) {
            const float4* mg = (const float4*)(memory + (size_t)b * TT * ENC_DIM);
            float4 acc = make_float4(0.f, 0.f, 0.f, 0.f);
            for (int t = 0; t < TT; t++) {
                const float4 v = mg[(size_t)t * (ENC_DIM / 4) + tid];
                acc.x += v.x; acc.y += v.y; acc.z += v.z; acc.w += v.w;
            }
            acc.x *= u; acc.y *= u; acc.z *= u; acc.w *= u;
            ((float4*)out_ctx)[tid] = acc;
        }
        __syncthreads();
    }
}

extern "C" void kernel_launch(void* const* d_in, const int* in_sizes, int n_in,
                              void* d_out, int out_size) {
    const float*         h      = (const float*)d_in[0];
    const float*         memory = (const float*)d_in[1];
    const float*         pm     = (const float*)d_in[2];
    const float*         awcat  = (const float*)d_in[3];
    const unsigned char* maskp  = (const unsigned char*)d_in[4];
    const int*           mlen   = (const int*)d_in[5];
    const float*         cpos   = (const float*)d_in[6];
    const float*         convw  = (const float*)d_in[7];
    const float*         densew = (const float*)d_in[8];
    const float*         queryw = (const float*)d_in[9];
    const float*         vw     = (const float*)d_in[10];
    const float*         posoff = (const float*)d_in[11];
    float* out = (float*)d_out;

    cudaFuncSetAttribute(attn_fused_kernel,
                         cudaFuncAttributeMaxDynamicSharedMemorySize, SMEM_BYTES);
    attn_fused_kernel<<<BB, 256, SMEM_BYTES>>>(h, memory, pm, awcat, maskp, mlen,
                                               cpos, convw, densew, queryw, vw,
                                               posoff, out);
}

// round 10
// speedup vs baseline: 1.6084x; 1.1269x over previous
#include <cuda_runtime.h>
#include <math.h>

#define BB 64
#define TT 2048
#define ENC_DIM 512
#define ATT_DIM 128
#define RNN_DIM 1024
#define N_FILT 32
#define KSIZE 31
#define PADC 15
#define WIN 32
#define WLMAX 65
#define NTL_PAD 36          // padded per-rank timestep rows (mult of 4)
#define DTP 129             // dense_t row stride (conflict-free)
#define AWLEN 66            // staged aw length per channel (36+30)

// ---- dynamic smem layout (floats), per CTA (one rank) ----
#define F_MEM  0                                   // 33*512 = 16896
#define F_PM   (F_MEM + 33 * ENC_DIM)              // 36*128 = 4608
#define F_DT   (F_PM + NTL_PAD * ATT_DIM)          // 32*129 = 4128
#define F_CWT  (F_DT + N_FILT * DTP)               // 62*32  = 1984
#define F_H    (F_CWT + KSIZE * 2 * N_FILT)        // 1024
#define F_CONV (F_H + RNN_DIM)                     // 32*36  = 1152
#define F_AW   (F_CONV + N_FILT * NTL_PAD)         // 2*96   = 192
#define F_Q    (F_AW + 2 * 96)                     // 128
#define F_V    (F_Q + ATT_DIM)                     // 128
#define F_E    (F_V + ATT_DIM)                     // 72
#define F_MK   (F_E + 72)                          // 40
#define F_W    (F_MK + 40)                         // 72
#define F_CTX  (F_W + 72)                          // 512
#define F_END  (F_CTX + ENC_DIM)
#define SMEM_BYTES (F_END * 4)                     // ~123.7 KB

__device__ __forceinline__ float ftanh(float x) {
    float a = fabsf(x);
    float t = __expf(-2.0f * a);
    float r = __fdividef(1.0f - t, 1.0f + t);
    return copysignf(r, x);
}

__device__ __forceinline__ void cp16(unsigned dst, const void* src) {
    asm volatile("cp.async.cg.shared.global [%0], [%1], 16;" :: "r"(dst), "l"(src));
}

__device__ __forceinline__ unsigned smem_u32(const void* p) {
    return (unsigned)__cvta_generic_to_shared(p);
}
__device__ __forceinline__ unsigned mapa_peer(unsigned addr, unsigned peer) {
    unsigned r;
    asm("mapa.shared::cluster.u32 %0, %1, %2;" : "=r"(r) : "r"(addr), "r"(peer));
    return r;
}
__device__ __forceinline__ void st_cluster_f32(unsigned addr, float v) {
    asm volatile("st.shared::cluster.f32 [%0], %1;" :: "r"(addr), "f"(v));
}
__device__ __forceinline__ void cluster_sync() {
    asm volatile("barrier.cluster.arrive.aligned;" ::: "memory");
    asm volatile("barrier.cluster.wait.aligned;" ::: "memory");
}

__global__ __launch_bounds__(256, 1) __cluster_dims__(2, 1, 1)
void attn_fused_kernel(
    const float* __restrict__ h,
    const float* __restrict__ memory,
    const float* __restrict__ pm,
    const float* __restrict__ awcat,
    const unsigned char* __restrict__ maskp,
    const int* __restrict__ mlen,
    const float* __restrict__ cpos,
    const float* __restrict__ convw,
    const float* __restrict__ densew,
    const float* __restrict__ queryw,
    const float* __restrict__ vw,
    const float* __restrict__ posoff,
    float* __restrict__ out)
{
    extern __shared__ float sm[];
    __shared__ int s_start, s_wl, s_fb;

    const int b    = blockIdx.x >> 1;
    const unsigned rank = blockIdx.x & 1;
    const unsigned peer = rank ^ 1;
    const int tid  = threadIdx.x;
    const int lane = tid & 31;
    const int wid  = tid >> 5;

    float* mem_sh  = sm + F_MEM;
    float* pm_sh   = sm + F_PM;
    float* dense_t = sm + F_DT;
    float* cwt_sh  = sm + F_CWT;
    float* h_sh    = sm + F_H;
    float* conv_sh = sm + F_CONV;
    float* aw0_sh  = sm + F_AW;
    float* aw1_sh  = sm + F_AW + 96;
    float* q_sh    = sm + F_Q;
    float* v_sh    = sm + F_V;
    float* e_sh    = sm + F_E;
    float* mk_sh   = sm + F_MK;
    float* w_sh    = sm + F_W;
    float* ctxbuf  = sm + F_CTX;

    // ---- phase 0: window calc + static staging ----
    if (tid == 0) {
        float cp      = cpos[b] + posoff[0];
        float max_end = (float)(mlen[b] - 1 - WIN);
        cp = fminf(fmaxf(cp, (float)WIN), max_end);
        float ms = rintf(fmaxf(cp - (float)WIN, 0.0f));
        int start = (int)ms;
        if (start < 0) start = 0;
        if (start > TT - 1) start = TT - 1;
        int end = start + 2 * WIN;
        if (end > TT - 1) end = TT - 1;
        s_start = start;
        s_wl    = end - start + 1;
    }
    {
        const float4* hg = (const float4*)(h + (size_t)b * RNN_DIM);
        ((float4*)h_sh)[tid] = hg[tid];
        for (int i = tid; i < N_FILT * 2 * KSIZE; i += 256) {
            int f = i / (2 * KSIZE), rr = i % (2 * KSIZE);
            int c = rr / KSIZE, k = rr % KSIZE;
            cwt_sh[(k * 2 + c) * N_FILT + f] = convw[i];
        }
        for (int i = tid; i < ATT_DIM * N_FILT; i += 256) {
            int a = i >> 5, f = i & 31;
            dense_t[f * DTP + a] = densew[i];
        }
        if (tid < ATT_DIM) v_sh[tid] = vw[tid];
    }
    __syncthreads();                          // S0
    const int start = s_start;
    const int wl    = s_wl;                   // == 65 for this problem shape
    const int TL0   = rank ? 33 : 0;          // own timestep offset
    int ntl = rank ? (wl - 33) : (wl < 33 ? wl : 33);
    if (ntl < 0) ntl = 0;

    // ---- phase 1: cp.async prefetch of own pm/mem slices; stage aw + mask ----
    {
        const unsigned pm_base  = smem_u32(pm_sh);
        const unsigned mem_base = smem_u32(mem_sh);
        const float4* pmsrc  = (const float4*)(pm + ((size_t)b * TT + start + TL0) * ATT_DIM);
        const float4* memsrc = (const float4*)(memory + ((size_t)b * TT + start + TL0) * ENC_DIM);
        const int n_pm4 = ntl * (ATT_DIM / 4);
        for (int i = tid; i < n_pm4; i += 256) cp16(pm_base + i * 16, pmsrc + i);
        asm volatile("cp.async.commit_group;");
        const int n_m4 = ntl * (ENC_DIM / 4);
        for (int i = tid; i < n_m4; i += 256) cp16(mem_base + i * 16, memsrc + i);
        asm volatile("cp.async.commit_group;");

        // aw slice: global positions start+TL0-15+jj, jj in [0,AWLEN)
        for (int j = tid; j < 2 * AWLEN; j += 256) {
            int c = (j >= AWLEN), jj = c ? j - AWLEN : j;
            int g = start + TL0 - PADC + jj;
            float v = (g >= 0 && g < TT) ? awcat[((size_t)b * 2 + c) * TT + g] : 0.f;
            (c ? aw1_sh : aw0_sh)[jj] = v;
        }
        if (tid < ntl) mk_sh[tid] = maskp[(size_t)b * TT + start + TL0 + tid] ? 1.f : 0.f;
    }

    // ---- phase 2: query GEMV, own 64 rows over 8 warps (4-row ILP) ----
    {
        const float4* h4 = (const float4*)h_sh;
        #pragma unroll 1
        for (int g = 0; g < 2; g++) {
            const int a0 = rank * 64 + wid * 8 + g * 4;
            const float4* r0 = (const float4*)(queryw + (size_t)a0 * RNN_DIM);
            const float4* r1 = (const float4*)(queryw + (size_t)(a0 + 1) * RNN_DIM);
            const float4* r2 = (const float4*)(queryw + (size_t)(a0 + 2) * RNN_DIM);
            const float4* r3 = (const float4*)(queryw + (size_t)(a0 + 3) * RNN_DIM);
            float acc0 = 0.f, acc1 = 0.f, acc2 = 0.f, acc3 = 0.f;
            #pragma unroll
            for (int k = 0; k < 8; k++) {
                const int idx = lane + k * 32;
                float4 hv = h4[idx];
                float4 w0 = r0[idx], w1 = r1[idx], w2 = r2[idx], w3 = r3[idx];
                acc0 += hv.x * w0.x + hv.y * w0.y + hv.z * w0.z + hv.w * w0.w;
                acc1 += hv.x * w1.x + hv.y * w1.y + hv.z * w1.z + hv.w * w1.w;
                acc2 += hv.x * w2.x + hv.y * w2.y + hv.z * w2.z + hv.w * w2.w;
                acc3 += hv.x * w3.x + hv.y * w3.y + hv.z * w3.z + hv.w * w3.w;
            }
            #pragma unroll
            for (int o = 16; o; o >>= 1) {
                acc0 += __shfl_down_sync(0xffffffffu, acc0, o);
                acc1 += __shfl_down_sync(0xffffffffu, acc1, o);
                acc2 += __shfl_down_sync(0xffffffffu, acc2, o);
                acc3 += __shfl_down_sync(0xffffffffu, acc3, o);
            }
            if (lane == 0) {
                q_sh[a0] = acc0; q_sh[a0 + 1] = acc1;
                q_sh[a0 + 2] = acc2; q_sh[a0 + 3] = acc3;
            }
        }
    }
    __syncthreads();                          // S1: aw + q_sh(own half) ready

    // ---- phase 3: conv (4 filters/warp, tl = lane, padded rows 0..35) ----
    {
        const int f0 = wid * 4;
        for (int tl = lane; tl < NTL_PAD; tl += 32) {
            float acc[4] = {0, 0, 0, 0};
            #pragma unroll
            for (int k = 0; k < KSIZE; k++) {
                const float a0v = aw0_sh[tl + k];
                const float a1v = aw1_sh[tl + k];
                const float4 w0 = *(const float4*)(cwt_sh + (k * 2 + 0) * N_FILT + f0);
                const float4 w1 = *(const float4*)(cwt_sh + (k * 2 + 1) * N_FILT + f0);
                acc[0] += a0v * w0.x + a1v * w1.x;
                acc[1] += a0v * w0.y + a1v * w1.y;
                acc[2] += a0v * w0.z + a1v * w1.z;
                acc[3] += a0v * w0.w + a1v * w1.w;
            }
            #pragma unroll
            for (int j = 0; j < 4; j++) conv_sh[(f0 + j) * NTL_PAD + tl] = acc[j];
        }
    }
    // exchange q halves: write own half into peer's q_sh
    if (tid < 64) {
        const unsigned q_peer = mapa_peer(smem_u32(q_sh), peer);
        st_cluster_f32(q_peer + 4 * (rank * 64 + tid), q_sh[rank * 64 + tid]);
    }
    asm volatile("cp.async.wait_group 1;");   // pm slice complete (this thread)
    __syncthreads();                          // S2: conv + all pm cp.asyncs
    cluster_sync();                           // C1: q halves exchanged

    // ---- phase 4: energies for own timesteps (4-t x 4-dim blocking) ----
    {
        const unsigned e_peer = mapa_peer(smem_u32(e_sh), peer);
        const float qv0 = q_sh[lane],      qv1 = q_sh[lane + 32];
        const float qv2 = q_sh[lane + 64], qv3 = q_sh[lane + 96];
        const float vv0 = v_sh[lane],      vv1 = v_sh[lane + 32];
        const float vv2 = v_sh[lane + 64], vv3 = v_sh[lane + 96];
        for (int t0 = wid * 4; t0 < ntl; t0 += 32) {
            float s[4][4];
            #pragma unroll
            for (int i = 0; i < 4; i++) {
                const float* p = pm_sh + (t0 + i) * ATT_DIM;   // padded rows: safe
                s[i][0] = qv0 + p[lane];
                s[i][1] = qv1 + p[lane + 32];
                s[i][2] = qv2 + p[lane + 64];
                s[i][3] = qv3 + p[lane + 96];
            }
            #pragma unroll
            for (int f = 0; f < N_FILT; f++) {
                const float4 c4 = *(const float4*)(conv_sh + f * NTL_PAD + t0);
                const float* dt = dense_t + f * DTP;
                const float d0 = dt[lane],      d1 = dt[lane + 32];
                const float d2 = dt[lane + 64], d3 = dt[lane + 96];
                s[0][0] += d0 * c4.x; s[0][1] += d1 * c4.x; s[0][2] += d2 * c4.x; s[0][3] += d3 * c4.x;
                s[1][0] += d0 * c4.y; s[1][1] += d1 * c4.y; s[1][2] += d2 * c4.y; s[1][3] += d3 * c4.y;
                s[2][0] += d0 * c4.z; s[2][1] += d1 * c4.z; s[2][2] += d2 * c4.z; s[2][3] += d3 * c4.z;
                s[3][0] += d0 * c4.w; s[3][1] += d1 * c4.w; s[3][2] += d2 * c4.w; s[3][3] += d3 * c4.w;
            }
            float a[4];
            #pragma unroll
            for (int i = 0; i < 4; i++)
                a[i] = vv0 * ftanh(s[i][0]) + vv1 * ftanh(s[i][1])
                     + vv2 * ftanh(s[i][2]) + vv3 * ftanh(s[i][3]);
            #pragma unroll
            for (int o = 16; o; o >>= 1) {
                a[0] += __shfl_xor_sync(0xffffffffu, a[0], o);
                a[1] += __shfl_xor_sync(0xffffffffu, a[1], o);
                a[2] += __shfl_xor_sync(0xffffffffu, a[2], o);
                a[3] += __shfl_xor_sync(0xffffffffu, a[3], o);
            }
            if (lane < 4 && t0 + lane < ntl) {
                float av = (lane == 0) ? a[0] : (lane == 1) ? a[1] : (lane == 2) ? a[2] : a[3];
                if (mk_sh[t0 + lane] != 0.f) av = -1e9f;
                const int eg = TL0 + t0 + lane;
                e_sh[eg] = av;
                st_cluster_f32(e_peer + 4 * eg, av);
            }
        }
    }
    __syncthreads();                          // S3
    cluster_sync();                           // C2: full e in both CTAs

    // ---- phase 5: softmax + new_pos (warp 0, both ranks redundantly) ----
    if (wid == 0) {
        float e0 = (lane < wl)      ? e_sh[lane]      : -3.4e38f;
        float e1 = (lane + 32 < wl) ? e_sh[lane + 32] : -3.4e38f;
        float e2 = (lane + 64 < wl) ? e_sh[lane + 64] : -3.4e38f;
        float m = fmaxf(e0, fmaxf(e1, e2));
        #pragma unroll
        for (int o = 16; o; o >>= 1) m = fmaxf(m, __shfl_xor_sync(0xffffffffu, m, o));
        if (m <= -1e9f) {
            if (lane == 0) s_fb = 1;
        } else {
            if (lane == 0) s_fb = 0;
            float x0 = (lane < wl)      ? __expf(e0 - m) : 0.f;
            float x1 = (lane + 32 < wl) ? __expf(e1 - m) : 0.f;
            float x2 = (lane + 64 < wl) ? __expf(e2 - m) : 0.f;
            float ssum = x0 + x1 + x2;
            float np = x0 * (float)(start + lane)
                     + x1 * (float)(start + lane + 32)
                     + x2 * (float)(start + lane + 64);
            #pragma unroll
            for (int o = 16; o; o >>= 1) {
                ssum += __shfl_xor_sync(0xffffffffu, ssum, o);
                np   += __shfl_xor_sync(0xffffffffu, np, o);
            }
            float inv = __fdividef(1.0f, ssum);
            if (lane < wl)      w_sh[lane]      = x0 * inv;
            if (lane + 32 < wl) w_sh[lane + 32] = x1 * inv;
            if (lane + 64 < wl) w_sh[lane + 64] = x2 * inv;
            if (lane == 0 && rank == 0)
                out[(size_t)BB * ENC_DIM + (size_t)BB * TT + b] = np * inv;
        }
    }
    asm volatile("cp.async.wait_group 0;");   // mem slice complete
    __syncthreads();                          // S4: w_sh + s_fb ready

    float* out_ctx = out + (size_t)b * ENC_DIM;
    float* out_w   = out + (size_t)BB * ENC_DIM + (size_t)b * TT;
    const int fb   = s_fb;

    // ---- phase 6: write own half of out_w in one select-pass ----
    {
        const float u = 1.0f / (float)TT;
        const int tbase = (int)rank * 1024 + tid * 4;
        float vals[4];
        #pragma unroll
        for (int j = 0; j < 4; j++) {
            const int tl = tbase + j - start;
            vals[j] = fb ? u : ((tl >= 0 && tl < wl) ? w_sh[tl] : 0.0f);
        }
        ((float4*)out_w)[rank * 256 + tid] = make_float4(vals[0], vals[1], vals[2], vals[3]);
        if (fb && rank == 0 && tid == 0)
            out[(size_t)BB * ENC_DIM + (size_t)BB * TT + b] = (float)(TT - 1) * 0.5f;
    }

    // ---- phase 7: context partial over own timesteps, DSMEM combine ----
    float4 acc = make_float4(0.f, 0.f, 0.f, 0.f);
    if (tid < 128) {
        if (!fb) {
            const float4* m4 = (const float4*)mem_sh;
            #pragma unroll 4
            for (int i = 0; i < ntl; i++) {
                const float wv = w_sh[TL0 + i];
                const float4 v = m4[i * (ENC_DIM / 4) + tid];
                acc.x += wv * v.x; acc.y += wv * v.y;
                acc.z += wv * v.z; acc.w += wv * v.w;
            }
        } else {
            const float u = 1.0f / (float)TT;
            const float4* mg = (const float4*)(memory
                + ((size_t)b * TT + (size_t)rank * 1024) * ENC_DIM);
            for (int t = 0; t < 1024; t++) {
                const float4 v = mg[(size_t)t * (ENC_DIM / 4) + tid];
                acc.x += v.x; acc.y += v.y; acc.z += v.z; acc.w += v.w;
            }
            acc.x *= u; acc.y *= u; acc.z *= u; acc.w *= u;
        }
    }
    if (rank == 1 && tid < 128) {
        const unsigned cb = mapa_peer(smem_u32(ctxbuf), peer) + tid * 16;
        st_cluster_f32(cb,      acc.x);
        st_cluster_f32(cb + 4,  acc.y);
        st_cluster_f32(cb + 8,  acc.z);
        st_cluster_f32(cb + 12, acc.w);
    }
    cluster_sync();                           // C3: rank1 partial visible
    if (rank == 0 && tid < 128) {
        const float4 p = ((const float4*)ctxbuf)[tid];
        acc.x += p.x; acc.y += p.y; acc.z += p.z; acc.w += p.w;
        ((float4*)out_ctx)[tid] = acc;
    }
}

extern "C" void kernel_launch(void* const* d_in, const int* in_sizes, int n_in,
                              void* d_out, int out_size) {
    const float*         h      = (const float*)d_in[0];
    const float*         memory = (const float*)d_in[1];
    const float*         pm     = (const float*)d_in[2];
    const float*         awcat  = (const float*)d_in[3];
    const unsigned char* maskp  = (const unsigned char*)d_in[4];
    const int*           mlen   = (const int*)d_in[5];
    const float*         cpos   = (const float*)d_in[6];
    const float*         convw  = (const float*)d_in[7];
    const float*         densew = (const float*)d_in[8];
    const float*         queryw = (const float*)d_in[9];
    const float*         vw     = (const float*)d_in[10];
    const float*         posoff = (const float*)d_in[11];
    float* out = (float*)d_out;

    cudaFuncSetAttribute(attn_fused_kernel,
                         cudaFuncAttributeMaxDynamicSharedMemorySize, SMEM_BYTES);
    attn_fused_kernel<<<2 * BB, 256, SMEM_BYTES>>>(h, memory, pm, awcat, maskp,
                                                   mlen, cpos, convw, densew,
                                                   queryw, vw, posoff, out);
}